// round 12
// baseline (speedup 1.0000x reference)
#include <cuda_runtime.h>
#include <math.h>

// Problem constants (fixed shapes)
#define NPG     100     // nodes per graph
#define EPG     1600    // edges per graph
#define NH      64      // hidden width
#define NINP    3
#define H2      32
#define NOUT    10
#define STRIDE  68      // feature row stride in floats (272B: 16B-aligned, bank-friendly)
#define NTHREADS 256

typedef unsigned long long ull;

// ---- packed f32x2 helpers (FFMA2 path; ptxas never emits these from C++) ----
__device__ __forceinline__ ull packf2(float lo, float hi) {
    ull r; asm("mov.b64 %0,{%1,%2};" : "=l"(r) : "f"(lo), "f"(hi)); return r;
}
__device__ __forceinline__ void unpackf2(ull v, float& lo, float& hi) {
    asm("mov.b64 {%0,%1},%2;" : "=f"(lo), "=f"(hi) : "l"(v));
}
__device__ __forceinline__ void fma2(ull& d, ull a, ull b) {
    asm("fma.rn.f32x2 %0,%1,%2,%0;" : "+l"(d) : "l"(a), "l"(b));
}
__device__ __forceinline__ ull mul2(ull a, ull b) {
    ull r; asm("mul.rn.f32x2 %0,%1,%2;" : "=l"(r) : "l"(a), "l"(b)); return r;
}
__device__ __forceinline__ ull add2(ull a, ull b) {
    ull r; asm("add.rn.f32x2 %0,%1,%2;" : "=l"(r) : "l"(a), "l"(b)); return r;
}

// ---------------- shared memory layout (floats) ----------------
// bufA 6800 | bufB 6800 | edata EPG*2 (float2/edge)
// then rowptr[104] cnt[104] dis[100] wsum[8] gv[64] hv[32] zv[16] gpool[256]
// NO Wbuf: gemm streams W from global (L2/L1-resident, shared by all CTAs).
struct SmemLayout {
    static constexpr int bufA_off   = 0;
    static constexpr int bufB_off   = NPG * STRIDE;
    static constexpr int edata_off  = bufB_off + NPG * STRIDE;     // 13600 (byte off %16==0)
    static constexpr int floats_end = edata_off + EPG * 2;         // 16800
    static constexpr int total_bytes =
        floats_end * 4 + (104 + 104 + 100 + 8 + 64 + 32 + 16 + 256) * 4 + 16;
};

// ---------------- Lhat (64-wide) via per-graph CSR gather, f32x2 ----------------
// Row ownership ALIGNED with gemm: warp rg owns rows {2rg, 2rg+1} + 16m —
// exactly the rows read by gemm threads with ty = 2rg, 2rg+1 (same warp).
// Leading __syncthreads covers the all-rows gather RAW (and WAR on dst);
// trailing __syncwarp is enough for the following same-warp gemm.
// 4-edge unroll, 4 independent FFMA2 accumulator chains (MLP 8).
__device__ __forceinline__ void lhat64(
    float* dst, const float* src, bool cheb,
    const float2* edata, const int* rowptr, float cl, int tid)
{
    __syncthreads();
    const int j  = tid & 31;
    const int rg = tid >> 5;          // 0..7
    const ull cl2 = packf2(cl, cl);
    const char* sbase = (const char*)src + j * 8;
    #pragma unroll 1
    for (int m = 0; m < NPG; m += 16) {
        #pragma unroll
        for (int h = 0; h < 2; h++) {
            const int i = m + 2 * rg + h;
            if (i < NPG) {
                ull a0 = mul2(cl2, *(const ull*)(src + i * STRIDE + 2 * j));
                ull a1 = packf2(0.f, 0.f), a2 = a1, a3 = a1;
                int e = rowptr[i];
                const int eEnd = rowptr[i + 1];
                for (; e + 3 < eEnd; e += 4) {
                    float2 ed0 = edata[e];                                  // LDS.64 bcast
                    float2 ed1 = edata[e + 1];
                    float2 ed2 = edata[e + 2];
                    float2 ed3 = edata[e + 3];
                    ull s0 = *(const ull*)(sbase + __float_as_int(ed0.y));  // LDS.64 gather
                    ull s1 = *(const ull*)(sbase + __float_as_int(ed1.y));
                    ull s2 = *(const ull*)(sbase + __float_as_int(ed2.y));
                    ull s3 = *(const ull*)(sbase + __float_as_int(ed3.y));
                    fma2(a0, packf2(ed0.x, ed0.x), s0);
                    fma2(a1, packf2(ed1.x, ed1.x), s1);
                    fma2(a2, packf2(ed2.x, ed2.x), s2);
                    fma2(a3, packf2(ed3.x, ed3.x), s3);
                }
                for (; e < eEnd; e++) {
                    float2 ed = edata[e];
                    ull s = *(const ull*)(sbase + __float_as_int(ed.y));
                    fma2(a0, packf2(ed.x, ed.x), s);
                }
                ull a = add2(add2(a0, a1), add2(a2, a3));
                float lo, hi; unpackf2(a, lo, hi);
                float* drow = dst + i * STRIDE + 2 * j;
                if (cheb) {
                    float2 d = *(float2*)drow;
                    *(float2*)drow = make_float2(2.0f * lo - d.x, 2.0f * hi - d.y);
                } else {
                    *(float2*)drow = make_float2(lo, hi);
                }
            }
        }
    }
    __syncwarp();
}

__device__ __forceinline__ void lhat3(
    float* dst, const float* src, bool cheb,
    const float2* edata, const int* rowptr, float cl, int tid)
{
    if (tid < NPG) {
        const int i = tid;
        const float* srow = src + i * STRIDE;
        float a0 = cl * srow[0], a1 = cl * srow[1], a2 = cl * srow[2];
        const int e1 = rowptr[i + 1];
        for (int e = rowptr[i]; e < e1; e++) {
            float2 ed = edata[e];
            const float* sc = (const float*)((const char*)src + __float_as_int(ed.y));
            a0 = fmaf(ed.x, sc[0], a0);
            a1 = fmaf(ed.x, sc[1], a1);
            a2 = fmaf(ed.x, sc[2], a2);
        }
        float* drow = dst + i * STRIDE;
        if (cheb) {
            drow[0] = 2.0f * a0 - drow[0];
            drow[1] = 2.0f * a1 - drow[1];
            drow[2] = 2.0f * a2 - drow[2];
        } else {
            drow[0] = a0; drow[1] = a1; drow[2] = a2;
        }
    }
    __syncthreads();
}

// ---------------- GEMM: acc[112x64] += Tx[.xCIN] @ W[CINx64] ----------------
// tx = tid&15 owns cols [4tx,4tx+4) (2 f32x2 pairs); ty = tid>>4 owns rows
// ty+16r, r=0..6 (row 96+ty valid only for ty<4). Rows 100..111 read stable
// out-of-row regions (never stored). W via LDG.128 (L1/L2-resident), no smem
// staging, NO BARRIERS inside gemm — all Tx rows it reads are own-warp rows.
template<int CIN>
__device__ __forceinline__ void gemm_acc(
    ull (&acc)[7][2], const float* __restrict__ Tx,
    const float* __restrict__ Wg, int tid)
{
    const int tx = tid & 15, ty = tid >> 4;
    const float4* W4 = (const float4*)Wg;         // 16 float4 per k-row
    if (CIN == 3) {
        #pragma unroll
        for (int k = 0; k < 3; k++) {
            float4 wv = __ldg(W4 + k * 16 + tx);
            ull wa = packf2(wv.x, wv.y), wb = packf2(wv.z, wv.w);
            #pragma unroll
            for (int r = 0; r < 7; r++) {
                float t = Tx[(ty + 16 * r) * STRIDE + k];
                ull t2 = packf2(t, t);
                fma2(acc[r][0], t2, wa);
                fma2(acc[r][1], t2, wb);
            }
        }
    } else {
        #pragma unroll 2
        for (int kc = 0; kc < CIN / 4; kc++) {
            float4 wv[4];
            #pragma unroll
            for (int q = 0; q < 4; q++)
                wv[q] = __ldg(W4 + (kc * 4 + q) * 16 + tx);   // LDG.128 (cache hit)
            ull w[4][2];
            #pragma unroll
            for (int q = 0; q < 4; q++) {
                w[q][0] = packf2(wv[q].x, wv[q].y);
                w[q][1] = packf2(wv[q].z, wv[q].w);
            }
            #pragma unroll
            for (int r = 0; r < 7; r++) {
                float4 tv = *(const float4*)(Tx + (ty + 16 * r) * STRIDE + kc * 4); // LDS.128 bcast
                ull t0 = packf2(tv.x, tv.x);
                fma2(acc[r][0], t0, w[0][0]); fma2(acc[r][1], t0, w[0][1]);
                ull t1 = packf2(tv.y, tv.y);
                fma2(acc[r][0], t1, w[1][0]); fma2(acc[r][1], t1, w[1][1]);
                ull t2 = packf2(tv.z, tv.z);
                fma2(acc[r][0], t2, w[2][0]); fma2(acc[r][1], t2, w[2][1]);
                ull t3 = packf2(tv.w, tv.w);
                fma2(acc[r][0], t3, w[3][0]); fma2(acc[r][1], t3, w[3][1]);
            }
        }
    }
}

// ---------------- One ChebConv layer (+bias +ReLU) -> bufA ----------------
// Sync structure: lhat64 carries a LEADING __syncthreads (all-rows gather) and
// trailing __syncwarp; gemm and the relu store need only same-warp ordering
// (row ownership aligned). lhat3 keeps its trailing __syncthreads.
template<int CIN>
__device__ __noinline__ void cheb_layer(
    float* bufA, float* bufB,
    const float* __restrict__ Wg, const float* __restrict__ bg,
    const float2* edata, const int* rowptr, float cl, int tid)
{
    ull acc[7][2];
    #pragma unroll
    for (int r = 0; r < 7; r++) { acc[r][0] = 0ull; acc[r][1] = 0ull; }

    gemm_acc<CIN>(acc, bufA, Wg, tid);                 // k=0: Tx0 = X
    if (CIN == 3) lhat3(bufB, bufA, false, edata, rowptr, cl, tid);
    else          lhat64(bufB, bufA, false, edata, rowptr, cl, tid);
    gemm_acc<CIN>(acc, bufB, Wg + 1 * CIN * 64, tid);  // k=1
    if (CIN == 3) lhat3(bufA, bufB, true, edata, rowptr, cl, tid);
    else          lhat64(bufA, bufB, true, edata, rowptr, cl, tid);
    gemm_acc<CIN>(acc, bufA, Wg + 2 * CIN * 64, tid);  // k=2
    if (CIN == 3) lhat3(bufB, bufA, true, edata, rowptr, cl, tid);
    else          lhat64(bufB, bufA, true, edata, rowptr, cl, tid);
    gemm_acc<CIN>(acc, bufB, Wg + 3 * CIN * 64, tid);  // k=3
    if (CIN == 3) lhat3(bufA, bufB, true, edata, rowptr, cl, tid);
    else          lhat64(bufA, bufB, true, edata, rowptr, cl, tid);
    gemm_acc<CIN>(acc, bufA, Wg + 4 * CIN * 64, tid);  // k=4

    // h = relu(acc + b) -> bufA (own-warp rows; warp is converged, so the
    // stores issue after all lanes' gemm loads)
    const int tx = tid & 15, ty = tid >> 4;
    float4 bb = __ldg((const float4*)(bg + tx * 4));
    #pragma unroll
    for (int r = 0; r < 7; r++) {
        if (r < 6 || ty < 4) {
            float v0, v1, v2, v3;
            unpackf2(acc[r][0], v0, v1);
            unpackf2(acc[r][1], v2, v3);
            float4 o = make_float4(fmaxf(v0 + bb.x, 0.f), fmaxf(v1 + bb.y, 0.f),
                                   fmaxf(v2 + bb.z, 0.f), fmaxf(v3 + bb.w, 0.f));
            *(float4*)(bufA + (ty + 16 * r) * STRIDE + tx * 4) = o;
        }
    }
    __syncwarp();   // next layer's gemm_0 reads these rows (same warp)
}

// ---------------- main kernel: one CTA per graph, 3 CTAs/SM ----------------
__global__ __launch_bounds__(NTHREADS, 3)
void chebnet_kernel(
    const float* __restrict__ x, const int* __restrict__ ei,
    const float* __restrict__ lambda_max,
    const float* __restrict__ W1, const float* __restrict__ b1,
    const float* __restrict__ W2, const float* __restrict__ b2,
    const float* __restrict__ W3, const float* __restrict__ b3,
    const float* __restrict__ bn_g, const float* __restrict__ bn_b,
    const float* __restrict__ bn_m, const float* __restrict__ bn_v,
    const float* __restrict__ fc1w, const float* __restrict__ fc1b,
    const float* __restrict__ fc2w, const float* __restrict__ fc2b,
    float* __restrict__ out, int E)
{
    extern __shared__ float smem_f[];
    float*  bufA   = smem_f + SmemLayout::bufA_off;
    float*  bufB   = smem_f + SmemLayout::bufB_off;
    float2* edata  = (float2*)(smem_f + SmemLayout::edata_off);
    int*    rowptr = (int*)(smem_f + SmemLayout::floats_end);
    int*    cnt    = rowptr + 104;
    float*  dis    = (float*)(cnt + 104);
    int*    wsum   = (int*)(dis + 100);
    float*  gv     = (float*)(wsum + 8);
    float*  hv     = gv + 64;
    float*  zv     = hv + 32;
    float*  gpool  = zv + 16;          // [4][64] partial pool sums

    const int g = blockIdx.x, tid = threadIdx.x;
    const int nbase = g * NPG, ebase = g * EPG;

    if (tid < NPG) cnt[tid] = 0;
    __syncthreads();

    // Pass 1: stage packed (src,dst) local edges in bufB, histogram per src row.
    int* stage = (int*)bufB;
    for (int e = tid; e < EPG; e += NTHREADS) {
        int s = ei[ebase + e] - nbase;
        int d = ei[E + ebase + e] - nbase;
        stage[e] = (s << 8) | d;
        atomicAdd(&cnt[s], 1);
    }
    // Load node features X into bufA (cols 0..2).
    for (int idx = tid; idx < NPG * NINP; idx += NTHREADS) {
        int i = idx / NINP, c = idx - i * NINP;
        bufA[i * STRIDE + c] = x[(nbase + i) * NINP + c];
    }
    __syncthreads();

    // Parallel exclusive scan of per-row degrees -> rowptr.
    const int deg = (tid < NPG) ? cnt[tid] : 0;
    if (tid < NPG) dis[tid] = (deg > 0) ? rsqrtf((float)deg) : 0.0f;
    {
        int v = deg;
        #pragma unroll
        for (int dlt = 1; dlt < 32; dlt <<= 1) {
            int n = __shfl_up_sync(0xFFFFFFFFu, v, dlt);
            if ((tid & 31) >= dlt) v += n;
        }
        if ((tid & 31) == 31) wsum[tid >> 5] = v;
        __syncthreads();
        int woff = 0;
        #pragma unroll
        for (int w = 0; w < 8; w++) woff += (w < (tid >> 5)) ? wsum[w] : 0;
        int incl = v + woff;
        if (tid < NPG)      rowptr[tid] = incl - deg;   // exclusive
        if (tid == NPG - 1) rowptr[NPG] = incl;
    }
    __syncthreads();
    if (tid < NPG) cnt[tid] = rowptr[tid];              // cursor
    const float lmx = lambda_max[g];
    const float s2  = 2.0f / lmx;
    const float cl  = s2 - 1.0f;
    __syncthreads();

    // Pass 2: CSR fill -> edata[e] = (coef, dst_byte_offset).
    for (int e = tid; e < EPG; e += NTHREADS) {
        int pk = stage[e];
        int s = pk >> 8, d = pk & 255;
        int pos = atomicAdd(&cnt[s], 1);
        float c = -s2 * dis[s] * dis[d];
        edata[pos] = make_float2(c, __int_as_float(d * (STRIDE * 4)));
    }
    __syncthreads();

    // 3 ChebConv layers
    cheb_layer<NINP>(bufA, bufB, W1, b1, edata, rowptr, cl, tid);
    cheb_layer<NH>  (bufA, bufB, W2, b2, edata, rowptr, cl, tid);
    cheb_layer<NH>  (bufA, bufB, W3, b3, edata, rowptr, cl, tid);

    __syncthreads();   // pool reads all rows cross-warp

    // mean pool (4-way parallel over rows) + BatchNorm (eval)
    {
        const int col = tid & 63, seg = tid >> 6;   // seg 0..3
        float s = 0.0f;
        for (int i = seg; i < NPG; i += 4) s += bufA[i * STRIDE + col];
        gpool[seg * 64 + col] = s;
    }
    __syncthreads();
    if (tid < NH) {
        float s = (gpool[tid] + gpool[64 + tid]) + (gpool[128 + tid] + gpool[192 + tid]);
        float gm = s * (1.0f / (float)NPG);
        gv[tid] = (gm - bn_m[tid]) * rsqrtf(bn_v[tid] + 1e-5f) * bn_g[tid] + bn_b[tid];
    }
    __syncthreads();
    if (tid < H2) {
        float a = fc1b[tid];
        for (int j = 0; j < NH; j++) a = fmaf(gv[j], fc1w[j * H2 + tid], a);
        hv[tid] = fmaxf(a, 0.0f);
    }
    __syncthreads();
    if (tid < NOUT) {
        float a = fc2b[tid];
        for (int m = 0; m < H2; m++) a = fmaf(hv[m], fc2w[m * NOUT + tid], a);
        zv[tid] = a;
    }
    __syncthreads();
    if (tid == 0) {
        float mx = zv[0];
        #pragma unroll
        for (int c = 1; c < NOUT; c++) mx = fmaxf(mx, zv[c]);
        float se = 0.0f;
        #pragma unroll
        for (int c = 0; c < NOUT; c++) se += expf(zv[c] - mx);
        float lse = mx + logf(se);
        #pragma unroll
        for (int c = 0; c < NOUT; c++) out[g * NOUT + c] = zv[c] - lse;
    }
}

extern "C" void kernel_launch(void* const* d_in, const int* in_sizes, int n_in,
                              void* d_out, int out_size)
{
    const float* x    = (const float*)d_in[0];
    const int*   ei   = (const int*)  d_in[1];
    const float* lmax = (const float*)d_in[3];
    const float* W1   = (const float*)d_in[4];
    const float* b1   = (const float*)d_in[5];
    const float* W2   = (const float*)d_in[6];
    const float* b2   = (const float*)d_in[7];
    const float* W3   = (const float*)d_in[8];
    const float* b3   = (const float*)d_in[9];
    const float* bn_g = (const float*)d_in[10];
    const float* bn_b = (const float*)d_in[11];
    const float* bn_m = (const float*)d_in[12];
    const float* bn_v = (const float*)d_in[13];
    const float* fc1w = (const float*)d_in[14];
    const float* fc1b = (const float*)d_in[15];
    const float* fc2w = (const float*)d_in[16];
    const float* fc2b = (const float*)d_in[17];
    float* out = (float*)d_out;

    const int E = in_sizes[1] / 2;
    const int G = in_sizes[3];

    const int smem_bytes = SmemLayout::total_bytes;
    cudaFuncSetAttribute(chebnet_kernel,
                         cudaFuncAttributeMaxDynamicSharedMemorySize, smem_bytes);

    chebnet_kernel<<<G, NTHREADS, smem_bytes>>>(
        x, ei, lmax, W1, b1, W2, b2, W3, b3,
        bn_g, bn_b, bn_m, bn_v, fc1w, fc1b, fc2w, fc2b, out, E);
}

// round 13
// speedup vs baseline: 1.1218x; 1.1218x over previous
#include <cuda_runtime.h>
#include <math.h>

// Problem constants (fixed shapes)
#define NPG     100     // nodes per graph
#define EPG     1600    // edges per graph
#define NH      64      // hidden width
#define NINP    3
#define H2      32
#define NOUT    10
#define STRIDE  68      // feature row stride in floats (272B: 16B-aligned, bank-friendly)
#define NTHREADS 256

typedef unsigned long long ull;

// ---- packed f32x2 helpers (FFMA2 path; ptxas never emits these from C++) ----
__device__ __forceinline__ ull packf2(float lo, float hi) {
    ull r; asm("mov.b64 %0,{%1,%2};" : "=l"(r) : "f"(lo), "f"(hi)); return r;
}
__device__ __forceinline__ void unpackf2(ull v, float& lo, float& hi) {
    asm("mov.b64 {%0,%1},%2;" : "=f"(lo), "=f"(hi) : "l"(v));
}
__device__ __forceinline__ void fma2(ull& d, ull a, ull b) {
    asm("fma.rn.f32x2 %0,%1,%2,%0;" : "+l"(d) : "l"(a), "l"(b));
}
__device__ __forceinline__ ull mul2(ull a, ull b) {
    ull r; asm("mul.rn.f32x2 %0,%1,%2;" : "=l"(r) : "l"(a), "l"(b)); return r;
}
__device__ __forceinline__ ull add2(ull a, ull b) {
    ull r; asm("add.rn.f32x2 %0,%1,%2;" : "=l"(r) : "l"(a), "l"(b)); return r;
}

// ---------------- shared memory layout (floats) ----------------
// bufA 6800 | bufB 6800 | edata EPG*2 (float2/edge)
// then rowptr[104] cnt[104] dis[100] wsum[8] gv[64] hv[32] zv[16] gpool[256]
// NO Wbuf: gemm streams W from global (L2/L1-resident, shared by all CTAs).
struct SmemLayout {
    static constexpr int bufA_off   = 0;
    static constexpr int bufB_off   = NPG * STRIDE;
    static constexpr int edata_off  = bufB_off + NPG * STRIDE;     // 13600 (byte off %16==0)
    static constexpr int floats_end = edata_off + EPG * 2;         // 16800
    static constexpr int total_bytes =
        floats_end * 4 + (104 + 104 + 100 + 8 + 64 + 32 + 16 + 256) * 4 + 16;
};

// ---------------- Lhat (64-wide) via per-graph CSR gather, f32x2 ----------------
// R10 structure (warp rg owns rows rg+8m, trailing __syncthreads), but the edge
// loop is 4-wide: 4 independent gathers in flight per iteration (MLP 4+).
// dst[i][:] = cheb ? 2*(cl*src[i] + sum coef*src[col]) - dst[i] : (...)
__device__ __forceinline__ void lhat64(
    float* dst, const float* src, bool cheb,
    const float2* edata, const int* rowptr, float cl, int tid)
{
    const int j  = tid & 31;          // lane: owns cols 2j, 2j+1
    const int rg = tid >> 5;          // warp: owns rows rg, rg+8, ...
    const ull cl2 = packf2(cl, cl);
    const char* sbase = (const char*)src + j * 8;
    for (int i = rg; i < NPG; i += 8) {
        ull a0 = mul2(cl2, *(const ull*)(src + i * STRIDE + 2 * j));
        ull a1 = packf2(0.f, 0.f);
        int e = rowptr[i];
        const int eEnd = rowptr[i + 1];
        for (; e + 3 < eEnd; e += 4) {
            float2 ed0 = edata[e];                                  // LDS.64 broadcast
            float2 ed1 = edata[e + 1];
            float2 ed2 = edata[e + 2];
            float2 ed3 = edata[e + 3];
            ull s0 = *(const ull*)(sbase + __float_as_int(ed0.y));  // LDS.64 gather, conflict-free
            ull s1 = *(const ull*)(sbase + __float_as_int(ed1.y));
            ull s2 = *(const ull*)(sbase + __float_as_int(ed2.y));
            ull s3 = *(const ull*)(sbase + __float_as_int(ed3.y));
            fma2(a0, packf2(ed0.x, ed0.x), s0);
            fma2(a1, packf2(ed1.x, ed1.x), s1);
            fma2(a0, packf2(ed2.x, ed2.x), s2);
            fma2(a1, packf2(ed3.x, ed3.x), s3);
        }
        for (; e < eEnd; e++) {
            float2 ed = edata[e];
            ull s = *(const ull*)(sbase + __float_as_int(ed.y));
            fma2(a0, packf2(ed.x, ed.x), s);
        }
        ull a = add2(a0, a1);
        float lo, hi; unpackf2(a, lo, hi);
        float* drow = dst + i * STRIDE + 2 * j;
        if (cheb) {
            float2 d = *(float2*)drow;
            *(float2*)drow = make_float2(2.0f * lo - d.x, 2.0f * hi - d.y);
        } else {
            *(float2*)drow = make_float2(lo, hi);
        }
    }
    __syncthreads();
}

__device__ __forceinline__ void lhat3(
    float* dst, const float* src, bool cheb,
    const float2* edata, const int* rowptr, float cl, int tid)
{
    if (tid < NPG) {
        const int i = tid;
        const float* srow = src + i * STRIDE;
        float a0 = cl * srow[0], a1 = cl * srow[1], a2 = cl * srow[2];
        const int e1 = rowptr[i + 1];
        for (int e = rowptr[i]; e < e1; e++) {
            float2 ed = edata[e];
            const float* sc = (const float*)((const char*)src + __float_as_int(ed.y));
            a0 = fmaf(ed.x, sc[0], a0);
            a1 = fmaf(ed.x, sc[1], a1);
            a2 = fmaf(ed.x, sc[2], a2);
        }
        float* drow = dst + i * STRIDE;
        if (cheb) {
            drow[0] = 2.0f * a0 - drow[0];
            drow[1] = 2.0f * a1 - drow[1];
            drow[2] = 2.0f * a2 - drow[2];
        } else {
            drow[0] = a0; drow[1] = a1; drow[2] = a2;
        }
    }
    __syncthreads();
}

// ---------------- GEMM: acc[112x64] += Tx[.xCIN] @ W[CINx64] ----------------
// tx = tid&15 owns cols [4tx,4tx+4) (2 f32x2 pairs); ty = tid>>4 owns rows
// ty+16r, r=0..6 (row 96+ty valid only for ty<4). Rows 100..111 compute
// garbage (reads stay inside smem) and are never stored.
// W read straight from global via LDG.128 (L1/L2-resident, shared by all CTAs);
// no smem staging, NO BARRIERS inside gemm.
template<int CIN>
__device__ __forceinline__ void gemm_acc(
    ull (&acc)[7][2], const float* __restrict__ Tx,
    const float* __restrict__ Wg, int tid)
{
    const int tx = tid & 15, ty = tid >> 4;
    const float4* W4 = (const float4*)Wg;         // 16 float4 per k-row
    if (CIN == 3) {
        #pragma unroll
        for (int k = 0; k < 3; k++) {
            float4 wv = __ldg(W4 + k * 16 + tx);
            ull wa = packf2(wv.x, wv.y), wb = packf2(wv.z, wv.w);
            #pragma unroll
            for (int r = 0; r < 7; r++) {
                float t = Tx[(ty + 16 * r) * STRIDE + k];
                ull t2 = packf2(t, t);
                fma2(acc[r][0], t2, wa);
                fma2(acc[r][1], t2, wb);
            }
        }
    } else {
        #pragma unroll 2
        for (int kc = 0; kc < CIN / 4; kc++) {
            float4 wv[4];
            #pragma unroll
            for (int q = 0; q < 4; q++)
                wv[q] = __ldg(W4 + (kc * 4 + q) * 16 + tx);   // LDG.128 (cache hit)
            ull w[4][2];
            #pragma unroll
            for (int q = 0; q < 4; q++) {
                w[q][0] = packf2(wv[q].x, wv[q].y);
                w[q][1] = packf2(wv[q].z, wv[q].w);
            }
            #pragma unroll
            for (int r = 0; r < 7; r++) {
                float4 tv = *(const float4*)(Tx + (ty + 16 * r) * STRIDE + kc * 4); // LDS.128 bcast
                ull t0 = packf2(tv.x, tv.x);
                fma2(acc[r][0], t0, w[0][0]); fma2(acc[r][1], t0, w[0][1]);
                ull t1 = packf2(tv.y, tv.y);
                fma2(acc[r][0], t1, w[1][0]); fma2(acc[r][1], t1, w[1][1]);
                ull t2 = packf2(tv.z, tv.z);
                fma2(acc[r][0], t2, w[2][0]); fma2(acc[r][1], t2, w[2][1]);
                ull t3 = packf2(tv.w, tv.w);
                fma2(acc[r][0], t3, w[3][0]); fma2(acc[r][1], t3, w[3][1]);
            }
        }
    }
}

// ---------------- One ChebConv layer (+bias +ReLU) -> bufA ----------------
// Hazards: every writer of bufA/bufB is separated from cross-thread readers by
// at least one lhat trailing __syncthreads (or the layer-end barrier).
template<int CIN>
__device__ __noinline__ void cheb_layer(
    float* bufA, float* bufB,
    const float* __restrict__ Wg, const float* __restrict__ bg,
    const float2* edata, const int* rowptr, float cl, int tid)
{
    ull acc[7][2];
    #pragma unroll
    for (int r = 0; r < 7; r++) { acc[r][0] = 0ull; acc[r][1] = 0ull; }

    gemm_acc<CIN>(acc, bufA, Wg, tid);                 // k=0: Tx0 = X
    if (CIN == 3) lhat3(bufB, bufA, false, edata, rowptr, cl, tid);
    else          lhat64(bufB, bufA, false, edata, rowptr, cl, tid);
    gemm_acc<CIN>(acc, bufB, Wg + 1 * CIN * 64, tid);  // k=1
    if (CIN == 3) lhat3(bufA, bufB, true, edata, rowptr, cl, tid);
    else          lhat64(bufA, bufB, true, edata, rowptr, cl, tid);
    gemm_acc<CIN>(acc, bufA, Wg + 2 * CIN * 64, tid);  // k=2
    if (CIN == 3) lhat3(bufB, bufA, true, edata, rowptr, cl, tid);
    else          lhat64(bufB, bufA, true, edata, rowptr, cl, tid);
    gemm_acc<CIN>(acc, bufB, Wg + 3 * CIN * 64, tid);  // k=3
    if (CIN == 3) lhat3(bufA, bufB, true, edata, rowptr, cl, tid);
    else          lhat64(bufA, bufB, true, edata, rowptr, cl, tid);
    gemm_acc<CIN>(acc, bufA, Wg + 4 * CIN * 64, tid);  // k=4

    // h = relu(acc + b) -> bufA (rows owned intra-warp; safe vs k=4 reads)
    const int tx = tid & 15, ty = tid >> 4;
    float4 bb = __ldg((const float4*)(bg + tx * 4));
    #pragma unroll
    for (int r = 0; r < 7; r++) {
        if (r < 6 || ty < 4) {
            float v0, v1, v2, v3;
            unpackf2(acc[r][0], v0, v1);
            unpackf2(acc[r][1], v2, v3);
            float4 o = make_float4(fmaxf(v0 + bb.x, 0.f), fmaxf(v1 + bb.y, 0.f),
                                   fmaxf(v2 + bb.z, 0.f), fmaxf(v3 + bb.w, 0.f));
            *(float4*)(bufA + (ty + 16 * r) * STRIDE + tx * 4) = o;
        }
    }
    __syncthreads();
}

// ---------------- main kernel: one CTA per graph, 3 CTAs/SM ----------------
__global__ __launch_bounds__(NTHREADS, 3)
void chebnet_kernel(
    const float* __restrict__ x, const int* __restrict__ ei,
    const float* __restrict__ lambda_max,
    const float* __restrict__ W1, const float* __restrict__ b1,
    const float* __restrict__ W2, const float* __restrict__ b2,
    const float* __restrict__ W3, const float* __restrict__ b3,
    const float* __restrict__ bn_g, const float* __restrict__ bn_b,
    const float* __restrict__ bn_m, const float* __restrict__ bn_v,
    const float* __restrict__ fc1w, const float* __restrict__ fc1b,
    const float* __restrict__ fc2w, const float* __restrict__ fc2b,
    float* __restrict__ out, int E)
{
    extern __shared__ float smem_f[];
    float*  bufA   = smem_f + SmemLayout::bufA_off;
    float*  bufB   = smem_f + SmemLayout::bufB_off;
    float2* edata  = (float2*)(smem_f + SmemLayout::edata_off);
    int*    rowptr = (int*)(smem_f + SmemLayout::floats_end);
    int*    cnt    = rowptr + 104;
    float*  dis    = (float*)(cnt + 104);
    int*    wsum   = (int*)(dis + 100);
    float*  gv     = (float*)(wsum + 8);
    float*  hv     = gv + 64;
    float*  zv     = hv + 32;
    float*  gpool  = zv + 16;          // [4][64] partial pool sums

    const int g = blockIdx.x, tid = threadIdx.x;
    const int nbase = g * NPG, ebase = g * EPG;

    if (tid < NPG) cnt[tid] = 0;
    __syncthreads();

    // Pass 1: stage packed (src,dst) local edges in bufB, histogram per src row.
    int* stage = (int*)bufB;
    for (int e = tid; e < EPG; e += NTHREADS) {
        int s = ei[ebase + e] - nbase;
        int d = ei[E + ebase + e] - nbase;
        stage[e] = (s << 8) | d;
        atomicAdd(&cnt[s], 1);
    }
    // Load node features X into bufA (cols 0..2).
    for (int idx = tid; idx < NPG * NINP; idx += NTHREADS) {
        int i = idx / NINP, c = idx - i * NINP;
        bufA[i * STRIDE + c] = x[(nbase + i) * NINP + c];
    }
    __syncthreads();

    // Parallel exclusive scan of per-row degrees -> rowptr.
    const int deg = (tid < NPG) ? cnt[tid] : 0;
    if (tid < NPG) dis[tid] = (deg > 0) ? rsqrtf((float)deg) : 0.0f;
    {
        int v = deg;
        #pragma unroll
        for (int dlt = 1; dlt < 32; dlt <<= 1) {
            int n = __shfl_up_sync(0xFFFFFFFFu, v, dlt);
            if ((tid & 31) >= dlt) v += n;
        }
        if ((tid & 31) == 31) wsum[tid >> 5] = v;
        __syncthreads();
        int woff = 0;
        #pragma unroll
        for (int w = 0; w < 8; w++) woff += (w < (tid >> 5)) ? wsum[w] : 0;
        int incl = v + woff;
        if (tid < NPG)      rowptr[tid] = incl - deg;   // exclusive
        if (tid == NPG - 1) rowptr[NPG] = incl;
    }
    __syncthreads();
    if (tid < NPG) cnt[tid] = rowptr[tid];              // cursor
    const float lmx = lambda_max[g];
    const float s2  = 2.0f / lmx;
    const float cl  = s2 - 1.0f;
    __syncthreads();

    // Pass 2: CSR fill -> edata[e] = (coef, dst_byte_offset).
    for (int e = tid; e < EPG; e += NTHREADS) {
        int pk = stage[e];
        int s = pk >> 8, d = pk & 255;
        int pos = atomicAdd(&cnt[s], 1);
        float c = -s2 * dis[s] * dis[d];
        edata[pos] = make_float2(c, __int_as_float(d * (STRIDE * 4)));
    }
    __syncthreads();

    // 3 ChebConv layers
    cheb_layer<NINP>(bufA, bufB, W1, b1, edata, rowptr, cl, tid);
    cheb_layer<NH>  (bufA, bufB, W2, b2, edata, rowptr, cl, tid);
    cheb_layer<NH>  (bufA, bufB, W3, b3, edata, rowptr, cl, tid);

    // mean pool (4-way parallel over rows) + BatchNorm (eval)
    {
        const int col = tid & 63, seg = tid >> 6;   // seg 0..3
        float s = 0.0f;
        for (int i = seg; i < NPG; i += 4) s += bufA[i * STRIDE + col];
        gpool[seg * 64 + col] = s;
    }
    __syncthreads();
    if (tid < NH) {
        float s = (gpool[tid] + gpool[64 + tid]) + (gpool[128 + tid] + gpool[192 + tid]);
        float gm = s * (1.0f / (float)NPG);
        gv[tid] = (gm - bn_m[tid]) * rsqrtf(bn_v[tid] + 1e-5f) * bn_g[tid] + bn_b[tid];
    }
    __syncthreads();
    if (tid < H2) {
        float a = fc1b[tid];
        for (int j = 0; j < NH; j++) a = fmaf(gv[j], fc1w[j * H2 + tid], a);
        hv[tid] = fmaxf(a, 0.0f);
    }
    __syncthreads();
    if (tid < NOUT) {
        float a = fc2b[tid];
        for (int m = 0; m < H2; m++) a = fmaf(hv[m], fc2w[m * NOUT + tid], a);
        zv[tid] = a;
    }
    __syncthreads();
    if (tid == 0) {
        float mx = zv[0];
        #pragma unroll
        for (int c = 1; c < NOUT; c++) mx = fmaxf(mx, zv[c]);
        float se = 0.0f;
        #pragma unroll
        for (int c = 0; c < NOUT; c++) se += expf(zv[c] - mx);
        float lse = mx + logf(se);
        #pragma unroll
        for (int c = 0; c < NOUT; c++) out[g * NOUT + c] = zv[c] - lse;
    }
}

extern "C" void kernel_launch(void* const* d_in, const int* in_sizes, int n_in,
                              void* d_out, int out_size)
{
    const float* x    = (const float*)d_in[0];
    const int*   ei   = (const int*)  d_in[1];
    const float* lmax = (const float*)d_in[3];
    const float* W1   = (const float*)d_in[4];
    const float* b1   = (const float*)d_in[5];
    const float* W2   = (const float*)d_in[6];
    const float* b2   = (const float*)d_in[7];
    const float* W3   = (const float*)d_in[8];
    const float* b3   = (const float*)d_in[9];
    const float* bn_g = (const float*)d_in[10];
    const float* bn_b = (const float*)d_in[11];
    const float* bn_m = (const float*)d_in[12];
    const float* bn_v = (const float*)d_in[13];
    const float* fc1w = (const float*)d_in[14];
    const float* fc1b = (const float*)d_in[15];
    const float* fc2w = (const float*)d_in[16];
    const float* fc2b = (const float*)d_in[17];
    float* out = (float*)d_out;

    const int E = in_sizes[1] / 2;
    const int G = in_sizes[3];

    const int smem_bytes = SmemLayout::total_bytes;
    cudaFuncSetAttribute(chebnet_kernel,
                         cudaFuncAttributeMaxDynamicSharedMemorySize, smem_bytes);

    chebnet_kernel<<<G, NTHREADS, smem_bytes>>>(
        x, ei, lmax, W1, b1, W2, b2, W3, b3,
        bn_g, bn_b, bn_m, bn_v, fc1w, fc1b, fc2w, fc2b, out, E);
}

// round 17
// speedup vs baseline: 1.1484x; 1.0238x over previous
#include <cuda_runtime.h>
#include <cuda_fp16.h>
#include <math.h>

// Problem constants (fixed shapes)
#define NPG     100     // nodes per graph
#define EPG     1600    // edges per graph
#define NH      64      // hidden width
#define NINP    3
#define H2      32
#define NOUT    10
#define STRIDE  68      // fp32 feature row stride in floats (272B)
#define SH_ROW  128     // fp16 shadow row stride in bytes (64 halves)
#define NTHREADS 256

typedef unsigned long long ull;

// ---- packed f32x2 helpers (FFMA2 path; ptxas never emits these from C++) ----
__device__ __forceinline__ ull packf2(float lo, float hi) {
    ull r; asm("mov.b64 %0,{%1,%2};" : "=l"(r) : "f"(lo), "f"(hi)); return r;
}
__device__ __forceinline__ void unpackf2(ull v, float& lo, float& hi) {
    asm("mov.b64 {%0,%1},%2;" : "=f"(lo), "=f"(hi) : "l"(v));
}
__device__ __forceinline__ void fma2(ull& d, ull a, ull b) {
    asm("fma.rn.f32x2 %0,%1,%2,%0;" : "+l"(d) : "l"(a), "l"(b));
}
__device__ __forceinline__ ull mul2(ull a, ull b) {
    ull r; asm("mul.rn.f32x2 %0,%1,%2;" : "=l"(r) : "l"(a), "l"(b)); return r;
}
__device__ __forceinline__ ull add2(ull a, ull b) {
    ull r; asm("add.rn.f32x2 %0,%1,%2;" : "=l"(r) : "l"(a), "l"(b)); return r;
}

// ---------------- shared memory layout ----------------
// floats: bufA 6800 | bufB 6800 | edata EPG*2 (float2/edge, .y = node index bits)
// then:   shA 12800B | shB 12800B (fp16 shadows, 128B rows, 128B-aligned)
// then:   rowptr[104] cnt[104] dis[100] wsum[8] gv[64] hv[32] zv[16] gpool[256]
struct SmemLayout {
    static constexpr int bufA_off   = 0;
    static constexpr int bufB_off   = NPG * STRIDE;
    static constexpr int edata_off  = bufB_off + NPG * STRIDE;     // 13600
    static constexpr int floats_end = edata_off + EPG * 2;         // 16800 (x4 = 67200, %128==0)
    static constexpr int shA_byte   = floats_end * 4;              // 67200
    static constexpr int shB_byte   = shA_byte + NPG * SH_ROW;     // 80000
    static constexpr int misc_byte  = shB_byte + NPG * SH_ROW;     // 92800
    static constexpr int total_bytes = misc_byte + (104 + 104 + 100 + 8 + 64 + 32 + 16 + 256) * 4 + 16;
};

// ---------------- Lhat (64-wide): gather from fp16 shadow, fp32 everywhere else --
// Warp rg owns rows rg+8m; lane j owns cols 2j,2j+1.
// dst fp32 (+ its fp16 shadow) ; src fp32 (diagonal) + srcH fp16 (gather).
// dst[i][:] = cheb ? 2*(cl*src[i] + sum coef*srcH[col]) - dst[i] : (...)
__device__ __forceinline__ void lhat64(
    float* dst, const float* src, __half* dstH, const __half* srcH, bool cheb,
    const float2* edata, const int* rowptr, float cl, int tid)
{
    const int j  = tid & 31;
    const int rg = tid >> 5;
    const ull cl2 = packf2(cl, cl);
    const char* hbase = (const char*)srcH + j * 4;   // this lane's half2 column
    for (int i = rg; i < NPG; i += 8) {
        ull a0 = mul2(cl2, *(const ull*)(src + i * STRIDE + 2 * j));  // fp32 diagonal
        ull a1 = packf2(0.f, 0.f);
        int e = rowptr[i];
        const int eEnd = rowptr[i + 1];
        for (; e + 1 < eEnd; e += 2) {
            float2 ed0 = edata[e];                                   // LDS.64 broadcast
            float2 ed1 = edata[e + 1];
            __half2 h0 = *(const __half2*)(hbase + (__float_as_int(ed0.y) << 7)); // LDS.32, 1 wf
            __half2 h1 = *(const __half2*)(hbase + (__float_as_int(ed1.y) << 7));
            float2 f0 = __half22float2(h0);
            float2 f1 = __half22float2(h1);
            fma2(a0, packf2(ed0.x, ed0.x), packf2(f0.x, f0.y));
            fma2(a1, packf2(ed1.x, ed1.x), packf2(f1.x, f1.y));
        }
        if (e < eEnd) {
            float2 ed = edata[e];
            __half2 h = *(const __half2*)(hbase + (__float_as_int(ed.y) << 7));
            float2 f = __half22float2(h);
            fma2(a0, packf2(ed.x, ed.x), packf2(f.x, f.y));
        }
        ull a = add2(a0, a1);
        float lo, hi; unpackf2(a, lo, hi);
        float* drow = dst + i * STRIDE + 2 * j;
        if (cheb) {
            float2 dv = *(float2*)drow;
            lo = 2.0f * lo - dv.x;
            hi = 2.0f * hi - dv.y;
        }
        *(float2*)drow = make_float2(lo, hi);
        *(__half2*)((char*)dstH + i * SH_ROW + j * 4) = __floats2half2_rn(lo, hi);
    }
    __syncthreads();
}

// 3-wide Lhat (layer 1): pure fp32 path, thread-per-row.
__device__ __forceinline__ void lhat3(
    float* dst, const float* src, bool cheb,
    const float2* edata, const int* rowptr, float cl, int tid)
{
    if (tid < NPG) {
        const int i = tid;
        const float* srow = src + i * STRIDE;
        float a0 = cl * srow[0], a1 = cl * srow[1], a2 = cl * srow[2];
        const int e1 = rowptr[i + 1];
        for (int e = rowptr[i]; e < e1; e++) {
            float2 ed = edata[e];
            const float* sc = src + __float_as_int(ed.y) * STRIDE;
            a0 = fmaf(ed.x, sc[0], a0);
            a1 = fmaf(ed.x, sc[1], a1);
            a2 = fmaf(ed.x, sc[2], a2);
        }
        float* drow = dst + i * STRIDE;
        if (cheb) {
            drow[0] = 2.0f * a0 - drow[0];
            drow[1] = 2.0f * a1 - drow[1];
            drow[2] = 2.0f * a2 - drow[2];
        } else {
            drow[0] = a0; drow[1] = a1; drow[2] = a2;
        }
    }
    __syncthreads();
}

// ---------------- GEMM: acc[112x64] += Tx[.xCIN] @ W[CINx64] (fp32) ----------
// tx = tid&15 owns cols [4tx,4tx+4); ty = tid>>4 owns rows ty+16r, r=0..6.
// W via LDG.128 (L1/L2-resident, shared by all CTAs); no barriers inside.
template<int CIN>
__device__ __forceinline__ void gemm_acc(
    ull (&acc)[7][2], const float* __restrict__ Tx,
    const float* __restrict__ Wg, int tid)
{
    const int tx = tid & 15, ty = tid >> 4;
    const float4* W4 = (const float4*)Wg;
    if (CIN == 3) {
        #pragma unroll
        for (int k = 0; k < 3; k++) {
            float4 wv = __ldg(W4 + k * 16 + tx);
            ull wa = packf2(wv.x, wv.y), wb = packf2(wv.z, wv.w);
            #pragma unroll
            for (int r = 0; r < 7; r++) {
                float t = Tx[(ty + 16 * r) * STRIDE + k];
                ull t2 = packf2(t, t);
                fma2(acc[r][0], t2, wa);
                fma2(acc[r][1], t2, wb);
            }
        }
    } else {
        #pragma unroll 2
        for (int kc = 0; kc < CIN / 4; kc++) {
            float4 wv[4];
            #pragma unroll
            for (int q = 0; q < 4; q++)
                wv[q] = __ldg(W4 + (kc * 4 + q) * 16 + tx);
            ull w[4][2];
            #pragma unroll
            for (int q = 0; q < 4; q++) {
                w[q][0] = packf2(wv[q].x, wv[q].y);
                w[q][1] = packf2(wv[q].z, wv[q].w);
            }
            #pragma unroll
            for (int r = 0; r < 7; r++) {
                float4 tv = *(const float4*)(Tx + (ty + 16 * r) * STRIDE + kc * 4);
                ull t0 = packf2(tv.x, tv.x);
                fma2(acc[r][0], t0, w[0][0]); fma2(acc[r][1], t0, w[0][1]);
                ull t1 = packf2(tv.y, tv.y);
                fma2(acc[r][0], t1, w[1][0]); fma2(acc[r][1], t1, w[1][1]);
                ull t2 = packf2(tv.z, tv.z);
                fma2(acc[r][0], t2, w[2][0]); fma2(acc[r][1], t2, w[2][1]);
                ull t3 = packf2(tv.w, tv.w);
                fma2(acc[r][0], t3, w[3][0]); fma2(acc[r][1], t3, w[3][1]);
            }
        }
    }
}

// ---------------- One ChebConv layer (+bias +ReLU) -> bufA (+shadow A) -------
template<int CIN>
__device__ __noinline__ void cheb_layer(
    float* bufA, float* bufB, __half* shA, __half* shB,
    const float* __restrict__ Wg, const float* __restrict__ bg,
    const float2* edata, const int* rowptr, float cl, int tid)
{
    ull acc[7][2];
    #pragma unroll
    for (int r = 0; r < 7; r++) { acc[r][0] = 0ull; acc[r][1] = 0ull; }

    gemm_acc<CIN>(acc, bufA, Wg, tid);                 // k=0: Tx0 = X
    if (CIN == 3) lhat3(bufB, bufA, false, edata, rowptr, cl, tid);
    else          lhat64(bufB, bufA, shB, shA, false, edata, rowptr, cl, tid);
    gemm_acc<CIN>(acc, bufB, Wg + 1 * CIN * 64, tid);  // k=1
    if (CIN == 3) lhat3(bufA, bufB, true, edata, rowptr, cl, tid);
    else          lhat64(bufA, bufB, shA, shB, true, edata, rowptr, cl, tid);
    gemm_acc<CIN>(acc, bufA, Wg + 2 * CIN * 64, tid);  // k=2
    if (CIN == 3) lhat3(bufB, bufA, true, edata, rowptr, cl, tid);
    else          lhat64(bufB, bufA, shB, shA, true, edata, rowptr, cl, tid);
    gemm_acc<CIN>(acc, bufB, Wg + 3 * CIN * 64, tid);  // k=3
    if (CIN == 3) lhat3(bufA, bufB, true, edata, rowptr, cl, tid);
    else          lhat64(bufA, bufB, shA, shB, true, edata, rowptr, cl, tid);
    gemm_acc<CIN>(acc, bufA, Wg + 4 * CIN * 64, tid);  // k=4

    // h = relu(acc + b) -> bufA + shadow A (rows owned intra-warp)
    const int tx = tid & 15, ty = tid >> 4;
    float4 bb = __ldg((const float4*)(bg + tx * 4));
    #pragma unroll
    for (int r = 0; r < 7; r++) {
        if (r < 6 || ty < 4) {
            float v0, v1, v2, v3;
            unpackf2(acc[r][0], v0, v1);
            unpackf2(acc[r][1], v2, v3);
            float4 o = make_float4(fmaxf(v0 + bb.x, 0.f), fmaxf(v1 + bb.y, 0.f),
                                   fmaxf(v2 + bb.z, 0.f), fmaxf(v3 + bb.w, 0.f));
            const int row = ty + 16 * r;
            *(float4*)(bufA + row * STRIDE + tx * 4) = o;
            __half2* hp = (__half2*)((char*)shA + row * SH_ROW + tx * 8);
            hp[0] = __floats2half2_rn(o.x, o.y);
            hp[1] = __floats2half2_rn(o.z, o.w);
        }
    }
    __syncthreads();
}

// ---------------- main kernel: one CTA per graph, 2 CTAs/SM ----------------
__global__ __launch_bounds__(NTHREADS, 2)
void chebnet_kernel(
    const float* __restrict__ x, const int* __restrict__ ei,
    const float* __restrict__ lambda_max,
    const float* __restrict__ W1, const float* __restrict__ b1,
    const float* __restrict__ W2, const float* __restrict__ b2,
    const float* __restrict__ W3, const float* __restrict__ b3,
    const float* __restrict__ bn_g, const float* __restrict__ bn_b,
    const float* __restrict__ bn_m, const float* __restrict__ bn_v,
    const float* __restrict__ fc1w, const float* __restrict__ fc1b,
    const float* __restrict__ fc2w, const float* __restrict__ fc2b,
    float* __restrict__ out, int E)
{
    extern __shared__ float smem_f[];
    float*  bufA   = smem_f + SmemLayout::bufA_off;
    float*  bufB   = smem_f + SmemLayout::bufB_off;
    float2* edata  = (float2*)(smem_f + SmemLayout::edata_off);
    __half* shA    = (__half*)((char*)smem_f + SmemLayout::shA_byte);
    __half* shB    = (__half*)((char*)smem_f + SmemLayout::shB_byte);
    int*    rowptr = (int*)((char*)smem_f + SmemLayout::misc_byte);
    int*    cnt    = rowptr + 104;
    float*  dis    = (float*)(cnt + 104);
    int*    wsum   = (int*)(dis + 100);
    float*  gv     = (float*)(wsum + 8);
    float*  hv     = gv + 64;
    float*  zv     = hv + 32;
    float*  gpool  = zv + 16;          // [4][64] partial pool sums

    const int g = blockIdx.x, tid = threadIdx.x;
    const int nbase = g * NPG, ebase = g * EPG;

    if (tid < NPG) cnt[tid] = 0;
    __syncthreads();

    // Pass 1: stage packed (src,dst) local edges in bufB, histogram per src row.
    int* stage = (int*)bufB;
    for (int e = tid; e < EPG; e += NTHREADS) {
        int s = ei[ebase + e] - nbase;
        int d = ei[E + ebase + e] - nbase;
        stage[e] = (s << 8) | d;
        atomicAdd(&cnt[s], 1);
    }
    // Load node features X into bufA (cols 0..2).
    for (int idx = tid; idx < NPG * NINP; idx += NTHREADS) {
        int i = idx / NINP, c = idx - i * NINP;
        bufA[i * STRIDE + c] = x[(nbase + i) * NINP + c];
    }
    __syncthreads();

    // Parallel exclusive scan of per-row degrees -> rowptr.
    const int deg = (tid < NPG) ? cnt[tid] : 0;
    if (tid < NPG) dis[tid] = (deg > 0) ? rsqrtf((float)deg) : 0.0f;
    {
        int v = deg;
        #pragma unroll
        for (int dlt = 1; dlt < 32; dlt <<= 1) {
            int n = __shfl_up_sync(0xFFFFFFFFu, v, dlt);
            if ((tid & 31) >= dlt) v += n;
        }
        if ((tid & 31) == 31) wsum[tid >> 5] = v;
        __syncthreads();
        int woff = 0;
        #pragma unroll
        for (int w = 0; w < 8; w++) woff += (w < (tid >> 5)) ? wsum[w] : 0;
        int incl = v + woff;
        if (tid < NPG)      rowptr[tid] = incl - deg;   // exclusive
        if (tid == NPG - 1) rowptr[NPG] = incl;
    }
    __syncthreads();
    if (tid < NPG) cnt[tid] = rowptr[tid];              // cursor
    const float lmx = lambda_max[g];
    const float s2  = 2.0f / lmx;
    const float cl  = s2 - 1.0f;
    __syncthreads();

    // Pass 2: CSR fill -> edata[e] = (coef fp32, dst node index bits).
    for (int e = tid; e < EPG; e += NTHREADS) {
        int pk = stage[e];
        int s = pk >> 8, d = pk & 255;
        int pos = atomicAdd(&cnt[s], 1);
        float c = -s2 * dis[s] * dis[d];
        edata[pos] = make_float2(c, __int_as_float(d));
    }
    __syncthreads();

    // 3 ChebConv layers
    cheb_layer<NINP>(bufA, bufB, shA, shB, W1, b1, edata, rowptr, cl, tid);
    cheb_layer<NH>  (bufA, bufB, shA, shB, W2, b2, edata, rowptr, cl, tid);
    cheb_layer<NH>  (bufA, bufB, shA, shB, W3, b3, edata, rowptr, cl, tid);

    // mean pool (4-way parallel over rows) + BatchNorm (eval)
    {
        const int col = tid & 63, seg = tid >> 6;   // seg 0..3
        float s = 0.0f;
        for (int i = seg; i < NPG; i += 4) s += bufA[i * STRIDE + col];
        gpool[seg * 64 + col] = s;
    }
    __syncthreads();
    if (tid < NH) {
        float s = (gpool[tid] + gpool[64 + tid]) + (gpool[128 + tid] + gpool[192 + tid]);
        float gm = s * (1.0f / (float)NPG);
        gv[tid] = (gm - bn_m[tid]) * rsqrtf(bn_v[tid] + 1e-5f) * bn_g[tid] + bn_b[tid];
    }
    __syncthreads();
    if (tid < H2) {
        float a = fc1b[tid];
        for (int j = 0; j < NH; j++) a = fmaf(gv[j], fc1w[j * H2 + tid], a);
        hv[tid] = fmaxf(a, 0.0f);
    }
    __syncthreads();
    if (tid < NOUT) {
        float a = fc2b[tid];
        for (int m = 0; m < H2; m++) a = fmaf(hv[m], fc2w[m * NOUT + tid], a);
        zv[tid] = a;
    }
    __syncthreads();
    if (tid == 0) {
        float mx = zv[0];
        #pragma unroll
        for (int c = 1; c < NOUT; c++) mx = fmaxf(mx, zv[c]);
        float se = 0.0f;
        #pragma unroll
        for (int c = 0; c < NOUT; c++) se += expf(zv[c] - mx);
        float lse = mx + logf(se);
        #pragma unroll
        for (int c = 0; c < NOUT; c++) out[g * NOUT + c] = zv[c] - lse;
    }
}

extern "C" void kernel_launch(void* const* d_in, const int* in_sizes, int n_in,
                              void* d_out, int out_size)
{
    const float* x    = (const float*)d_in[0];
    const int*   ei   = (const int*)  d_in[1];
    const float* lmax = (const float*)d_in[3];
    const float* W1   = (const float*)d_in[4];
    const float* b1   = (const float*)d_in[5];
    const float* W2   = (const float*)d_in[6];
    const float* b2   = (const float*)d_in[7];
    const float* W3   = (const float*)d_in[8];
    const float* b3   = (const float*)d_in[9];
    const float* bn_g = (const float*)d_in[10];
    const float* bn_b = (const float*)d_in[11];
    const float* bn_m = (const float*)d_in[12];
    const float* bn_v = (const float*)d_in[13];
    const float* fc1w = (const float*)d_in[14];
    const float* fc1b = (const float*)d_in[15];
    const float* fc2w = (const float*)d_in[16];
    const float* fc2b = (const float*)d_in[17];
    float* out = (float*)d_out;

    const int E = in_sizes[1] / 2;
    const int G = in_sizes[3];

    const int smem_bytes = SmemLayout::total_bytes;
    cudaFuncSetAttribute(chebnet_kernel,
                         cudaFuncAttributeMaxDynamicSharedMemorySize, smem_bytes);

    chebnet_kernel<<<G, NTHREADS, smem_bytes>>>(
        x, ei, lmax, W1, b1, W2, b2, W3, b3,
        bn_g, bn_b, bn_m, bn_v, fc1w, fc1b, fc2w, fc2b, out, E);
}